// round 14
// baseline (speedup 1.0000x reference)
#include <cuda_runtime.h>
#include <cuda_bf16.h>
#include <math.h>
#include <stdint.h>

#define N_NODES 50000
#define N_EDGES 800000
#define D 64
#define GRID 148             // co-resident (1 CTA/SM) for grid barrier
#define RANGE 338            // ceil(N_NODES / GRID)
#define N_TILES 391          // ceil(N_NODES/128)
#define THREADS 256

// ---- smem layout (u32 units for frags; byte offsets) -------------------------
#define U_WIH_HI 0
#define U_WIH_LO 6144
#define U_WHH_HI 12288
#define U_WHH_LO 18432
#define U_WW_HI  24576
#define U_WW_LO  26624
#define U_TOTAL  28672                       // 114,688 B
#define OFF_BRZ  (U_TOTAL * 4)               // f32[128]
#define OFF_BNI  (OFF_BRZ + 512)             // f32[64]
#define OFF_BNH  (OFF_BNI + 256)             // f32[64]
#define OFF_BB   (OFF_BNH + 256)             // f32[64]
#define SMEM_BYTES (OFF_BB + 256)

// ---- device scratch (device-code-only references; R1/2 ATS lesson) -----------
__device__ float    g_agg[N_NODES * D];
__device__ int      g_rowptr[N_NODES + 1];
__device__ int      g_cnt[N_NODES];          // zero at load; fill re-zeroes
__device__ int      g_cursor[N_NODES];
__device__ int      g_srcsorted[N_EDGES];
__device__ int      g_chunksum[GRID];
__device__ int      g_chunkoff[GRID];
__device__ uint32_t g_wihF[2][6144];         // [hi/lo] B-fragment layout
__device__ uint32_t g_whhF[2][6144];
__device__ uint32_t g_wF[2][2048];
__device__ float    g_brz[128];
__device__ float    g_bni[64];
__device__ float    g_bnh[64];
__device__ int          g_bar_count;
__device__ volatile int g_bar_gen;

// ---- helpers ------------------------------------------------------------------
__device__ __forceinline__ float sigmoid_fast(float x) {
    return __fdividef(1.0f, 1.0f + __expf(-x));
}
__device__ __forceinline__ float tanh_fast(float x) {
    return 1.0f - __fdividef(2.0f, __expf(2.0f * x) + 1.0f);
}
__device__ __forceinline__ uint32_t pack_bf2(__nv_bfloat16 a, __nv_bfloat16 b) {
    __nv_bfloat162 p = __halves2bfloat162(a, b);
    return *reinterpret_cast<uint32_t*>(&p);
}
__device__ __forceinline__ void split2(float2 v, uint32_t& h, uint32_t& l) {
    __nv_bfloat16 h0 = __float2bfloat16(v.x);
    __nv_bfloat16 l0 = __float2bfloat16(v.x - __bfloat162float(h0));
    __nv_bfloat16 h1 = __float2bfloat16(v.y);
    __nv_bfloat16 l1 = __float2bfloat16(v.y - __bfloat162float(h1));
    h = pack_bf2(h0, h1);
    l = pack_bf2(l0, l1);
}
__device__ __forceinline__ float2 unsplit2(uint32_t h, uint32_t l) {
    __nv_bfloat162 hb = *reinterpret_cast<__nv_bfloat162*>(&h);
    __nv_bfloat162 lb = *reinterpret_cast<__nv_bfloat162*>(&l);
    return make_float2(__bfloat162float(hb.x) + __bfloat162float(lb.x),
                       __bfloat162float(hb.y) + __bfloat162float(lb.y));
}

__device__ __forceinline__ void mma16816(float* c, const uint32_t* a,
                                         uint32_t b0, uint32_t b1) {
    asm volatile(
        "mma.sync.aligned.m16n8k16.row.col.f32.bf16.bf16.f32 "
        "{%0,%1,%2,%3}, {%4,%5,%6,%7}, {%8,%9}, {%0,%1,%2,%3};"
        : "+f"(c[0]), "+f"(c[1]), "+f"(c[2]), "+f"(c[3])
        : "r"(a[0]), "r"(a[1]), "r"(a[2]), "r"(a[3]), "r"(b0), "r"(b1));
}

__device__ __forceinline__ void gemm_block(
    float C[8][4], const uint32_t* Ahi, const uint32_t* Alo,
    const uint32_t* whi, const uint32_t* wlo, int ntBase, int lane) {
#pragma unroll
    for (int kt = 0; kt < 4; kt++) {
        const uint32_t* ah = Ahi + 4 * kt;
        const uint32_t* al = Alo + 4 * kt;
#pragma unroll
        for (int nt = 0; nt < 8; nt++) {
            int idx = (((ntBase + nt) * 4 + kt) * 32 + lane) * 2;
            uint32_t bh0 = whi[idx], bh1 = whi[idx + 1];
            uint32_t bl0 = wlo[idx], bl1 = wlo[idx + 1];
            mma16816(C[nt], ah, bh0, bh1);
            mma16816(C[nt], ah, bl0, bl1);
            mma16816(C[nt], al, bh0, bh1);
        }
    }
}

__device__ __forceinline__ void load_x_frags(
    const float* __restrict__ X, int r0, int r1, int tig,
    uint32_t* hi, uint32_t* lo) {
    bool v0 = (r0 < N_NODES), v1 = (r1 < N_NODES);
    const float2 z2 = make_float2(0.f, 0.f);
#pragma unroll
    for (int kt = 0; kt < 4; kt++) {
        int cb = 16 * kt + 2 * tig;
        float2 p0 = v0 ? *(const float2*)&X[(size_t)r0 * 64 + cb]     : z2;
        float2 p1 = v1 ? *(const float2*)&X[(size_t)r1 * 64 + cb]     : z2;
        float2 p2 = v0 ? *(const float2*)&X[(size_t)r0 * 64 + cb + 8] : z2;
        float2 p3 = v1 ? *(const float2*)&X[(size_t)r1 * 64 + cb + 8] : z2;
        split2(p0, hi[4 * kt + 0], lo[4 * kt + 0]);
        split2(p1, hi[4 * kt + 1], lo[4 * kt + 1]);
        split2(p2, hi[4 * kt + 2], lo[4 * kt + 2]);
        split2(p3, hi[4 * kt + 3], lo[4 * kt + 3]);
    }
}

// grid barrier (148 co-resident CTAs; validated R10/R11)
__device__ __forceinline__ void grid_sync() {
    __syncthreads();
    if (threadIdx.x == 0) {
        __threadfence();
        int gen = g_bar_gen;
        if (atomicAdd(&g_bar_count, 1) == GRID - 1) {
            g_bar_count = 0;
            __threadfence();
            g_bar_gen = gen + 1;
        } else {
            while (g_bar_gen == gen) { __nanosleep(32); }
        }
        __threadfence();
    }
    __syncthreads();
}

__device__ __forceinline__ int block_incl_scan(int v) {
    __shared__ int ws[16];
    int lane = threadIdx.x & 31, w = threadIdx.x >> 5;
    int x = v;
#pragma unroll
    for (int off = 1; off < 32; off <<= 1) {
        int y = __shfl_up_sync(0xffffffffu, x, off);
        if (lane >= off) x += y;
    }
    if (lane == 31) ws[w] = x;
    __syncthreads();
    if (w == 0 && lane < 16) {
        int s = ws[lane];
        int xs = s;
#pragma unroll
        for (int off = 1; off < 16; off <<= 1) {
            int y = __shfl_up_sync(0xffffu, xs, off);
            if (lane >= off) xs += y;
        }
        ws[lane] = xs - s;
    }
    __syncthreads();
    int res = x + ws[w];
    __syncthreads();
    return res;
}

// ------------------------- prep + count (merged) ------------------------------
__device__ __forceinline__ void put_wfrag(uint32_t* hiArr, uint32_t* loArr,
                                          const float* Wmat, int n, int k0) {
    int nt = n >> 3, g = n & 7;
    int kt = k0 >> 4, rem = k0 & 15;
    int breg = (rem >= 8) ? 1 : 0;
    int tig = (rem >> 1) & 3;
    int idx = ((nt * 4 + kt) * 32 + (g * 4 + tig)) * 2 + breg;
    uint32_t h, l;
    split2(make_float2(Wmat[n * 64 + k0], Wmat[n * 64 + k0 + 1]), h, l);
    hiArr[idx] = h;
    loArr[idx] = l;
}

__global__ void prep_kernel(const float* __restrict__ W,
                            const float* __restrict__ Wih,
                            const float* __restrict__ Whh,
                            const float* __restrict__ bih,
                            const float* __restrict__ bhh,
                            const int* __restrict__ dst) {
    int i = blockIdx.x * blockDim.x + threadIdx.x;
    if (i < 6144) {
        put_wfrag(g_wihF[0], g_wihF[1], Wih, i >> 5, 2 * (i & 31));
    } else if (i < 12288) {
        int e = i - 6144;
        put_wfrag(g_whhF[0], g_whhF[1], Whh, e >> 5, 2 * (e & 31));
    } else if (i < 14336) {
        int e = i - 12288;
        put_wfrag(g_wF[0], g_wF[1], W, e >> 5, 2 * (e & 31));
    } else if (i < 14464) {
        int d = i - 14336;
        g_brz[d] = bih[d] + bhh[d];
    } else if (i < 14528) {
        int d = i - 14464;
        g_bni[d] = bih[128 + d];
    } else if (i < 14592) {
        int d = i - 14528;
        g_bnh[d] = bhh[128 + d];
    }
    // in-degree count (g_cnt is zero: module-load init / fill re-zero)
    if (i < N_EDGES) atomicAdd(&g_cnt[dst[i]], 1);
}

// ------------------------- CSR: 3-phase scan -----------------------------------
__global__ void __launch_bounds__(512) csr_scan_kernel() {
    int cta = blockIdx.x, t = threadIdx.x;
    {
        int i = cta * RANGE + t;
        int v = (t < RANGE && i < N_NODES) ? g_cnt[i] : 0;
        int incl = block_incl_scan(v);
        if (t == 511) g_chunksum[cta] = incl;
    }
    grid_sync();
    if (cta == 0) {
        int v = (t < GRID) ? g_chunksum[t] : 0;
        int incl = block_incl_scan(v);
        if (t < GRID) g_chunkoff[t] = incl - v;
    }
    grid_sync();
    {
        int i = cta * RANGE + t;
        int v = (t < RANGE && i < N_NODES) ? g_cnt[i] : 0;
        int incl = block_incl_scan(v) + g_chunkoff[cta];
        if (t < RANGE && i < N_NODES) {
            g_rowptr[i + 1] = incl;
            g_cursor[i]     = incl - v;
        }
        if (cta == 0 && t == 0) g_rowptr[0] = 0;
    }
}

__global__ void fill_kernel(const int* __restrict__ src, const int* __restrict__ dst) {
    int e = blockIdx.x * blockDim.x + threadIdx.x;
    if (e < N_EDGES) {
        int dd = dst[e];
        int pos = atomicAdd(&g_cursor[dd], 1);
        g_srcsorted[pos] = src[e];
    }
    if (e < N_NODES) g_cnt[e] = 0;   // restore zero invariant for next replay
}

// ------------------------- persistent 3-step mega GRU --------------------------
// 148 CTAs x 256 threads, 1 CTA/SM. Per step: agg phase (warp/node, unroll-16:
// 8 warps x 16 x 256B / 240cyc = 136 B/cyc/SM >> LTS cap -> throughput-bound),
// grid_sync, HMMA gru phase (R13), grid_sync.
__global__ void __launch_bounds__(THREADS) mega_kernel(
    const float* __restrict__ node_in, float* __restrict__ hout,
    const float* __restrict__ b) {
    extern __shared__ uint32_t smu[];
    float* sbrz = (float*)((char*)smu + OFF_BRZ);
    float* sbni = (float*)((char*)smu + OFF_BNI);
    float* sbnh = (float*)((char*)smu + OFF_BNH);
    float* sbb  = (float*)((char*)smu + OFF_BB);

    int t = threadIdx.x;
    int lane = t & 31;
    int w = t >> 5;
    int g = lane >> 2;
    int tig = lane & 3;

    // ---- prologue: weight fragments + biases, once per CTA for all 3 steps ----
    {
        uint4* d = (uint4*)smu;
        const uint4* s;
        s = (const uint4*)g_wihF[0];
        for (int i = t; i < 1536; i += THREADS) d[i] = s[i];
        s = (const uint4*)g_wihF[1];
        for (int i = t; i < 1536; i += THREADS) d[U_WIH_LO / 4 + i] = s[i];
        s = (const uint4*)g_whhF[0];
        for (int i = t; i < 1536; i += THREADS) d[U_WHH_HI / 4 + i] = s[i];
        s = (const uint4*)g_whhF[1];
        for (int i = t; i < 1536; i += THREADS) d[U_WHH_LO / 4 + i] = s[i];
        s = (const uint4*)g_wF[0];
        for (int i = t; i < 512; i += THREADS) d[U_WW_HI / 4 + i] = s[i];
        s = (const uint4*)g_wF[1];
        for (int i = t; i < 512; i += THREADS) d[U_WW_LO / 4 + i] = s[i];
    }
    if (t < 128) sbrz[t] = g_brz[t];
    else if (t < 192) sbni[t - 128] = g_bni[t - 128];
    else if (t < 256) sbnh[t - 192] = g_bnh[t - 192];
    if (t < 64) sbb[t] = b[t];
    __syncthreads();

    const uint32_t* WIHh = smu + U_WIH_HI;
    const uint32_t* WIHl = smu + U_WIH_LO;
    const uint32_t* WHHh = smu + U_WHH_HI;
    const uint32_t* WHHl = smu + U_WHH_LO;
    const uint32_t* WWh  = smu + U_WW_HI;
    const uint32_t* WWl  = smu + U_WW_LO;

    const float* hcur = node_in;
    for (int step = 0; step < 3; step++) {
        // ================= agg phase: one warp per node ====================
        int gw0 = blockIdx.x * 8 + w;
        for (int n = gw0; n < N_NODES; n += GRID * 8) {
            int p = g_rowptr[n];
            int e = g_rowptr[n + 1];
            float ax = 0.f, ay = 0.f;
            for (; p + 16 <= e; p += 16) {
                float2 m[16];
#pragma unroll
                for (int j = 0; j < 16; j++) {
                    int s = g_srcsorted[p + j];
                    m[j] = *(const float2*)&hcur[(size_t)s * 64 + lane * 2];
                }
#pragma unroll
                for (int j = 0; j < 16; j++) { ax += m[j].x; ay += m[j].y; }
            }
            for (; p + 4 <= e; p += 4) {
                float2 m[4];
#pragma unroll
                for (int j = 0; j < 4; j++) {
                    int s = g_srcsorted[p + j];
                    m[j] = *(const float2*)&hcur[(size_t)s * 64 + lane * 2];
                }
#pragma unroll
                for (int j = 0; j < 4; j++) { ax += m[j].x; ay += m[j].y; }
            }
            for (; p < e; p++) {
                int s = g_srcsorted[p];
                float2 m0 = *(const float2*)&hcur[(size_t)s * 64 + lane * 2];
                ax += m0.x; ay += m0.y;
            }
            *(float2*)&g_agg[(size_t)n * 64 + lane * 2] = make_float2(ax, ay);
        }
        grid_sync();

        // ================= HMMA gru phase (R13) ============================
        for (int tile = blockIdx.x; tile < N_TILES; tile += GRID) {
            int R0 = tile * 128 + w * 16;
            int r0 = R0 + g;
            int r1 = R0 + g + 8;

            uint32_t Ahi[16], Alo[16];
            uint32_t Hhi[16], Hlo[16];
            load_x_frags(g_agg, r0, r1, tig, Ahi, Alo);
            load_x_frags(hcur,  r0, r1, tig, Hhi, Hlo);

            float deg0 = (r0 < N_NODES) ? (float)(g_rowptr[r0 + 1] - g_rowptr[r0]) : 0.f;
            float deg1 = (r1 < N_NODES) ? (float)(g_rowptr[r1 + 1] - g_rowptr[r1]) : 0.f;

            // A-GEMM: C_A = hagg @ W^T + deg*b
            float CA[8][4];
#pragma unroll
            for (int nt = 0; nt < 8; nt++)
#pragma unroll
                for (int j = 0; j < 4; j++) CA[nt][j] = 0.f;
            gemm_block(CA, Ahi, Alo, WWh, WWl, 0, lane);
#pragma unroll
            for (int nt = 0; nt < 8; nt++) {
                int c = 8 * nt + 2 * tig;
                CA[nt][0] += deg0 * sbb[c];
                CA[nt][1] += deg0 * sbb[c + 1];
                CA[nt][2] += deg1 * sbb[c];
                CA[nt][3] += deg1 * sbb[c + 1];
            }
#pragma unroll
            for (int kt = 0; kt < 4; kt++) {
                split2(make_float2(CA[2 * kt][0],     CA[2 * kt][1]),
                       Ahi[4 * kt + 0], Alo[4 * kt + 0]);
                split2(make_float2(CA[2 * kt][2],     CA[2 * kt][3]),
                       Ahi[4 * kt + 1], Alo[4 * kt + 1]);
                split2(make_float2(CA[2 * kt + 1][0], CA[2 * kt + 1][1]),
                       Ahi[4 * kt + 2], Alo[4 * kt + 2]);
                split2(make_float2(CA[2 * kt + 1][2], CA[2 * kt + 1][3]),
                       Ahi[4 * kt + 3], Alo[4 * kt + 3]);
            }

            // R gate
            float P[8][4];
            float CB[8][4];
#pragma unroll
            for (int nt = 0; nt < 8; nt++)
#pragma unroll
                for (int j = 0; j < 4; j++) P[nt][j] = 0.f;
            gemm_block(P, Ahi, Alo, WIHh, WIHl, 0, lane);
            gemm_block(P, Hhi, Hlo, WHHh, WHHl, 0, lane);
#pragma unroll
            for (int nt = 0; nt < 8; nt++) {
                int c = 8 * nt + 2 * tig;
                P[nt][0] = sigmoid_fast(P[nt][0] + sbrz[c]);
                P[nt][1] = sigmoid_fast(P[nt][1] + sbrz[c + 1]);
                P[nt][2] = sigmoid_fast(P[nt][2] + sbrz[c]);
                P[nt][3] = sigmoid_fast(P[nt][3] + sbrz[c + 1]);
            }

            // h_n
#pragma unroll
            for (int nt = 0; nt < 8; nt++)
#pragma unroll
                for (int j = 0; j < 4; j++) CB[nt][j] = 0.f;
            gemm_block(CB, Hhi, Hlo, WHHh, WHHl, 16, lane);
#pragma unroll
            for (int nt = 0; nt < 8; nt++) {
                int c = 8 * nt + 2 * tig;
                P[nt][0] *= (CB[nt][0] + sbnh[c]);
                P[nt][1] *= (CB[nt][1] + sbnh[c + 1]);
                P[nt][2] *= (CB[nt][2] + sbnh[c]);
                P[nt][3] *= (CB[nt][3] + sbnh[c + 1]);
            }

            // i_n
#pragma unroll
            for (int nt = 0; nt < 8; nt++)
#pragma unroll
                for (int j = 0; j < 4; j++) CB[nt][j] = 0.f;
            gemm_block(CB, Ahi, Alo, WIHh, WIHl, 16, lane);
#pragma unroll
            for (int nt = 0; nt < 8; nt++) {
                int c = 8 * nt + 2 * tig;
                P[nt][0] = tanh_fast(CB[nt][0] + sbni[c]     + P[nt][0]);
                P[nt][1] = tanh_fast(CB[nt][1] + sbni[c + 1] + P[nt][1]);
                P[nt][2] = tanh_fast(CB[nt][2] + sbni[c]     + P[nt][2]);
                P[nt][3] = tanh_fast(CB[nt][3] + sbni[c + 1] + P[nt][3]);
            }

            // Z gate + output
#pragma unroll
            for (int nt = 0; nt < 8; nt++)
#pragma unroll
                for (int j = 0; j < 4; j++) CB[nt][j] = 0.f;
            gemm_block(CB, Ahi, Alo, WIHh, WIHl, 8, lane);
            gemm_block(CB, Hhi, Hlo, WHHh, WHHl, 8, lane);
#pragma unroll
            for (int nt = 0; nt < 8; nt++) {
                int c = 8 * nt + 2 * tig;
                float z0 = sigmoid_fast(CB[nt][0] + sbrz[64 + c]);
                float z1 = sigmoid_fast(CB[nt][1] + sbrz[64 + c + 1]);
                float z2 = sigmoid_fast(CB[nt][2] + sbrz[64 + c]);
                float z3 = sigmoid_fast(CB[nt][3] + sbrz[64 + c + 1]);
                int fb = 4 * (nt >> 1) + ((nt & 1) ? 2 : 0);
                float2 hrow0 = unsplit2(Hhi[fb],     Hlo[fb]);
                float2 hrow1 = unsplit2(Hhi[fb + 1], Hlo[fb + 1]);
                float o0 = (1.f - z0) * P[nt][0] + z0 * hrow0.x;
                float o1 = (1.f - z1) * P[nt][1] + z1 * hrow0.y;
                float o2 = (1.f - z2) * P[nt][2] + z2 * hrow1.x;
                float o3 = (1.f - z3) * P[nt][3] + z3 * hrow1.y;
                if (r0 < N_NODES)
                    *(float2*)&hout[(size_t)r0 * 64 + c] = make_float2(o0, o1);
                if (r1 < N_NODES)
                    *(float2*)&hout[(size_t)r1 * 64 + c] = make_float2(o2, o3);
            }
        }
        if (step < 2) grid_sync();
        hcur = hout;
    }
}

// ------------------------- launch ----------------------------------------------
extern "C" void kernel_launch(void* const* d_in, const int* in_sizes, int n_in,
                              void* d_out, int out_size) {
    const float *node_in = 0, *W = 0, *b = 0, *Wih = 0, *Whh = 0, *bih = 0, *bhh = 0;
    const int *src = 0, *dst = 0;
    int n12288 = 0, n192 = 0, n800k = 0;
    for (int i = 0; i < n_in; i++) {
        switch (in_sizes[i]) {
            case N_NODES * D: node_in = (const float*)d_in[i]; break;
            case D * D:       W = (const float*)d_in[i]; break;
            case D:           b = (const float*)d_in[i]; break;
            case 3 * D * D:
                if (n12288++ == 0) Wih = (const float*)d_in[i];
                else               Whh = (const float*)d_in[i];
                break;
            case 3 * D:
                if (n192++ == 0) bih = (const float*)d_in[i];
                else             bhh = (const float*)d_in[i];
                break;
            case N_EDGES:
                if (n800k++ == 0) src = (const int*)d_in[i];
                else              dst = (const int*)d_in[i];
                break;
            default: break;
        }
    }
    float* h = (float*)d_out;

    cudaFuncSetAttribute(mega_kernel, cudaFuncAttributeMaxDynamicSharedMemorySize,
                         SMEM_BYTES);

    prep_kernel<<<(N_EDGES + 255) / 256, 256>>>(W, Wih, Whh, bih, bhh, dst);
    csr_scan_kernel<<<GRID, 512>>>();
    fill_kernel<<<(N_EDGES + 255) / 256, 256>>>(src, dst);
    mega_kernel<<<GRID, THREADS, SMEM_BYTES>>>(node_in, h, b);
}

// round 15
// speedup vs baseline: 1.6473x; 1.6473x over previous
#include <cuda_runtime.h>
#include <cuda_bf16.h>
#include <math.h>
#include <stdint.h>

#define N_NODES 50000
#define N_EDGES 800000
#define D 64
#define SCAN_GRID 148
#define RANGE 338
#define N_TILES 391          // ceil(N_NODES/128)
#define GRU_GRID 131
#define THREADS 256

// ---- smem layout (u32 units for frags; byte offsets) -------------------------
#define U_WIH_HI 0
#define U_WIH_LO 6144
#define U_WHH_HI 12288
#define U_WHH_LO 18432
#define U_WW_HI  24576
#define U_WW_LO  26624
#define U_TOTAL  28672                       // 114,688 B
#define OFF_BRZ  (U_TOTAL * 4)               // f32[128]
#define OFF_BNI  (OFF_BRZ + 512)             // f32[64]
#define OFF_BNH  (OFF_BNI + 256)             // f32[64]
#define OFF_BB   (OFF_BNH + 256)             // f32[64]
#define SMEM_BYTES (OFF_BB + 256)

// ---- device scratch (device-code-only references; R1/2 ATS lesson) -----------
__device__ float    g_agg[N_NODES * D];
__device__ int      g_rowptr[N_NODES + 1];
__device__ int      g_cnt[N_NODES];          // zero at load; fill re-zeroes
__device__ int      g_cursor[N_NODES];
__device__ int      g_srcsorted[N_EDGES];
__device__ int      g_chunksum[SCAN_GRID];
__device__ int      g_chunkoff[SCAN_GRID];
__device__ uint32_t g_wihF[2][6144];         // [hi/lo] B-fragment layout
__device__ uint32_t g_whhF[2][6144];
__device__ uint32_t g_wF[2][2048];
__device__ float    g_brz[128];
__device__ float    g_bni[64];
__device__ float    g_bnh[64];
__device__ int          g_bar_count;
__device__ volatile int g_bar_gen;

// ---- helpers ------------------------------------------------------------------
__device__ __forceinline__ float sigmoid_fast(float x) {
    return __fdividef(1.0f, 1.0f + __expf(-x));
}
__device__ __forceinline__ float tanh_fast(float x) {
    return 1.0f - __fdividef(2.0f, __expf(2.0f * x) + 1.0f);
}
__device__ __forceinline__ uint32_t pack_bf2(__nv_bfloat16 a, __nv_bfloat16 b) {
    __nv_bfloat162 p = __halves2bfloat162(a, b);
    return *reinterpret_cast<uint32_t*>(&p);
}
__device__ __forceinline__ void split2(float2 v, uint32_t& h, uint32_t& l) {
    __nv_bfloat16 h0 = __float2bfloat16(v.x);
    __nv_bfloat16 l0 = __float2bfloat16(v.x - __bfloat162float(h0));
    __nv_bfloat16 h1 = __float2bfloat16(v.y);
    __nv_bfloat16 l1 = __float2bfloat16(v.y - __bfloat162float(h1));
    h = pack_bf2(h0, h1);
    l = pack_bf2(l0, l1);
}
__device__ __forceinline__ float2 unsplit2(uint32_t h, uint32_t l) {
    __nv_bfloat162 hb = *reinterpret_cast<__nv_bfloat162*>(&h);
    __nv_bfloat162 lb = *reinterpret_cast<__nv_bfloat162*>(&l);
    return make_float2(__bfloat162float(hb.x) + __bfloat162float(lb.x),
                       __bfloat162float(hb.y) + __bfloat162float(lb.y));
}

// warp-level bf16 MMA: D[16,8] += A[16,16] * B[16,8]
__device__ __forceinline__ void mma16816(float* c, const uint32_t* a,
                                         uint32_t b0, uint32_t b1) {
    asm volatile(
        "mma.sync.aligned.m16n8k16.row.col.f32.bf16.bf16.f32 "
        "{%0,%1,%2,%3}, {%4,%5,%6,%7}, {%8,%9}, {%0,%1,%2,%3};"
        : "+f"(c[0]), "+f"(c[1]), "+f"(c[2]), "+f"(c[3])
        : "r"(a[0]), "r"(a[1]), "r"(a[2]), "r"(a[3]), "r"(b0), "r"(b1));
}

// accumulate 8-ntile block: C += X * W^T (3-product split)
__device__ __forceinline__ void gemm_block(
    float C[8][4], const uint32_t* Ahi, const uint32_t* Alo,
    const uint32_t* whi, const uint32_t* wlo, int ntBase, int lane) {
#pragma unroll
    for (int kt = 0; kt < 4; kt++) {
        const uint32_t* ah = Ahi + 4 * kt;
        const uint32_t* al = Alo + 4 * kt;
#pragma unroll
        for (int nt = 0; nt < 8; nt++) {
            int idx = (((ntBase + nt) * 4 + kt) * 32 + lane) * 2;
            uint32_t bh0 = whi[idx], bh1 = whi[idx + 1];
            uint32_t bl0 = wlo[idx], bl1 = wlo[idx + 1];
            mma16816(C[nt], ah, bh0, bh1);   // hi*hi
            mma16816(C[nt], ah, bl0, bl1);   // hi*lo
            mma16816(C[nt], al, bh0, bh1);   // lo*hi
        }
    }
}

// load 16-row x 64-col X slice as split A-fragments (rows r0,r1 = g,g+8)
__device__ __forceinline__ void load_x_frags(
    const float* __restrict__ X, int r0, int r1, int tig,
    uint32_t* hi, uint32_t* lo) {
    bool v0 = (r0 < N_NODES), v1 = (r1 < N_NODES);
    const float2 z2 = make_float2(0.f, 0.f);
#pragma unroll
    for (int kt = 0; kt < 4; kt++) {
        int cb = 16 * kt + 2 * tig;
        float2 p0 = v0 ? *(const float2*)&X[(size_t)r0 * 64 + cb]     : z2;
        float2 p1 = v1 ? *(const float2*)&X[(size_t)r1 * 64 + cb]     : z2;
        float2 p2 = v0 ? *(const float2*)&X[(size_t)r0 * 64 + cb + 8] : z2;
        float2 p3 = v1 ? *(const float2*)&X[(size_t)r1 * 64 + cb + 8] : z2;
        split2(p0, hi[4 * kt + 0], lo[4 * kt + 0]);
        split2(p1, hi[4 * kt + 1], lo[4 * kt + 1]);
        split2(p2, hi[4 * kt + 2], lo[4 * kt + 2]);
        split2(p3, hi[4 * kt + 3], lo[4 * kt + 3]);
    }
}

// grid barrier (148 co-resident CTAs; validated R10/R11)
__device__ __forceinline__ void grid_sync() {
    __syncthreads();
    if (threadIdx.x == 0) {
        __threadfence();
        int gen = g_bar_gen;
        if (atomicAdd(&g_bar_count, 1) == SCAN_GRID - 1) {
            g_bar_count = 0;
            __threadfence();
            g_bar_gen = gen + 1;
        } else {
            while (g_bar_gen == gen) { __nanosleep(32); }
        }
        __threadfence();
    }
    __syncthreads();
}

__device__ __forceinline__ int block_incl_scan(int v) {
    __shared__ int ws[16];
    int lane = threadIdx.x & 31, w = threadIdx.x >> 5;
    int x = v;
#pragma unroll
    for (int off = 1; off < 32; off <<= 1) {
        int y = __shfl_up_sync(0xffffffffu, x, off);
        if (lane >= off) x += y;
    }
    if (lane == 31) ws[w] = x;
    __syncthreads();
    if (w == 0 && lane < 16) {
        int s = ws[lane];
        int xs = s;
#pragma unroll
        for (int off = 1; off < 16; off <<= 1) {
            int y = __shfl_up_sync(0xffffu, xs, off);
            if (lane >= off) xs += y;
        }
        ws[lane] = xs - s;
    }
    __syncthreads();
    int res = x + ws[w];
    __syncthreads();
    return res;
}

// ------------------------- prep + count (merged; validated in R14) -----------
__device__ __forceinline__ void put_wfrag(uint32_t* hiArr, uint32_t* loArr,
                                          const float* Wmat, int n, int k0) {
    int nt = n >> 3, g = n & 7;
    int kt = k0 >> 4, rem = k0 & 15;
    int breg = (rem >= 8) ? 1 : 0;
    int tig = (rem >> 1) & 3;
    int idx = ((nt * 4 + kt) * 32 + (g * 4 + tig)) * 2 + breg;
    uint32_t h, l;
    split2(make_float2(Wmat[n * 64 + k0], Wmat[n * 64 + k0 + 1]), h, l);
    hiArr[idx] = h;
    loArr[idx] = l;
}

__global__ void prep_kernel(const float* __restrict__ W,
                            const float* __restrict__ Wih,
                            const float* __restrict__ Whh,
                            const float* __restrict__ bih,
                            const float* __restrict__ bhh,
                            const int* __restrict__ dst) {
    int i = blockIdx.x * blockDim.x + threadIdx.x;
    if (i < 6144) {
        put_wfrag(g_wihF[0], g_wihF[1], Wih, i >> 5, 2 * (i & 31));
    } else if (i < 12288) {
        int e = i - 6144;
        put_wfrag(g_whhF[0], g_whhF[1], Whh, e >> 5, 2 * (e & 31));
    } else if (i < 14336) {
        int e = i - 12288;
        put_wfrag(g_wF[0], g_wF[1], W, e >> 5, 2 * (e & 31));
    } else if (i < 14464) {
        int d = i - 14336;
        g_brz[d] = bih[d] + bhh[d];
    } else if (i < 14528) {
        int d = i - 14464;
        g_bni[d] = bih[128 + d];
    } else if (i < 14592) {
        int d = i - 14528;
        g_bnh[d] = bhh[128 + d];
    }
    // in-degree count (g_cnt zero invariant: module-load init / fill re-zero)
    if (i < N_EDGES) atomicAdd(&g_cnt[dst[i]], 1);
}

// ------------------------- CSR: 3-phase scan -----------------------------------
__global__ void __launch_bounds__(512) csr_scan_kernel() {
    int cta = blockIdx.x, t = threadIdx.x;
    {
        int i = cta * RANGE + t;
        int v = (t < RANGE && i < N_NODES) ? g_cnt[i] : 0;
        int incl = block_incl_scan(v);
        if (t == 511) g_chunksum[cta] = incl;
    }
    grid_sync();
    if (cta == 0) {
        int v = (t < SCAN_GRID) ? g_chunksum[t] : 0;
        int incl = block_incl_scan(v);
        if (t < SCAN_GRID) g_chunkoff[t] = incl - v;
    }
    grid_sync();
    {
        int i = cta * RANGE + t;
        int v = (t < RANGE && i < N_NODES) ? g_cnt[i] : 0;
        int incl = block_incl_scan(v) + g_chunkoff[cta];
        if (t < RANGE && i < N_NODES) {
            g_rowptr[i + 1] = incl;
            g_cursor[i]     = incl - v;
        }
        if (cta == 0 && t == 0) g_rowptr[0] = 0;
    }
}

__global__ void fill_kernel(const int* __restrict__ src, const int* __restrict__ dst) {
    int e = blockIdx.x * blockDim.x + threadIdx.x;
    if (e < N_EDGES) {
        int dd = dst[e];
        int pos = atomicAdd(&g_cursor[dd], 1);
        g_srcsorted[pos] = src[e];
    }
    if (e < N_NODES) g_cnt[e] = 0;   // restore zero invariant for next replay
}

// ------------------------- aggregation of raw h: one warp per node -----------
// MUST stay a standalone high-occupancy kernel (R7/R10/R14: fusing it into the
// register-heavy GRU kernel drops occupancy/regs and goes latency-bound).
__global__ void __launch_bounds__(256) agg_kernel(const float* __restrict__ hsrc) {
    int gw = (blockIdx.x * blockDim.x + threadIdx.x) >> 5;
    if (gw >= N_NODES) return;
    int lane = threadIdx.x & 31;
    int p = g_rowptr[gw];
    int e = g_rowptr[gw + 1];
    float ax = 0.0f, ay = 0.0f;
    for (; p + 8 <= e; p += 8) {
        float2 m[8];
#pragma unroll
        for (int j = 0; j < 8; j++) {
            int s = g_srcsorted[p + j];
            m[j] = *(const float2*)&hsrc[(size_t)s * 64 + lane * 2];
        }
#pragma unroll
        for (int j = 0; j < 8; j++) { ax += m[j].x; ay += m[j].y; }
    }
    for (; p < e; p++) {
        int s = g_srcsorted[p];
        float2 m0 = *(const float2*)&hsrc[(size_t)s * 64 + lane * 2];
        ax += m0.x; ay += m0.y;
    }
    *(float2*)&g_agg[(size_t)gw * 64 + lane * 2] = make_float2(ax, ay);
}

// ------------------------- HMMA GRU (R13, unchanged) --------------------------
__global__ void __launch_bounds__(THREADS) gru_kernel(
    const float* __restrict__ hin, float* __restrict__ hout,
    const float* __restrict__ b) {
    extern __shared__ uint32_t smu[];
    float* sbrz = (float*)((char*)smu + OFF_BRZ);
    float* sbni = (float*)((char*)smu + OFF_BNI);
    float* sbnh = (float*)((char*)smu + OFF_BNH);
    float* sbb  = (float*)((char*)smu + OFF_BB);

    int t = threadIdx.x;
    int lane = t & 31;
    int w = t >> 5;
    int g = lane >> 2;
    int tig = lane & 3;

    // ---- prologue: copy weight fragments + biases (once per CTA) ----
    {
        uint4* d = (uint4*)smu;
        const uint4* s;
        s = (const uint4*)g_wihF[0];
        for (int i = t; i < 1536; i += THREADS) d[i] = s[i];
        s = (const uint4*)g_wihF[1];
        for (int i = t; i < 1536; i += THREADS) d[U_WIH_LO / 4 + i] = s[i];
        s = (const uint4*)g_whhF[0];
        for (int i = t; i < 1536; i += THREADS) d[U_WHH_HI / 4 + i] = s[i];
        s = (const uint4*)g_whhF[1];
        for (int i = t; i < 1536; i += THREADS) d[U_WHH_LO / 4 + i] = s[i];
        s = (const uint4*)g_wF[0];
        for (int i = t; i < 512; i += THREADS) d[U_WW_HI / 4 + i] = s[i];
        s = (const uint4*)g_wF[1];
        for (int i = t; i < 512; i += THREADS) d[U_WW_LO / 4 + i] = s[i];
    }
    if (t < 128) sbrz[t] = g_brz[t];
    else if (t < 192) sbni[t - 128] = g_bni[t - 128];
    else if (t < 256) sbnh[t - 192] = g_bnh[t - 192];
    if (t < 64) sbb[t] = b[t];
    __syncthreads();

    const uint32_t* WIHh = smu + U_WIH_HI;
    const uint32_t* WIHl = smu + U_WIH_LO;
    const uint32_t* WHHh = smu + U_WHH_HI;
    const uint32_t* WHHl = smu + U_WHH_LO;
    const uint32_t* WWh  = smu + U_WW_HI;
    const uint32_t* WWl  = smu + U_WW_LO;

    for (int tile = blockIdx.x; tile < N_TILES; tile += gridDim.x) {
        int R0 = tile * 128 + w * 16;
        int r0 = R0 + g;
        int r1 = R0 + g + 8;

        // ---- operand fragments ----
        uint32_t Ahi[16], Alo[16];   // hagg -> later A (post-GEMM)
        uint32_t Hhi[16], Hlo[16];   // h
        load_x_frags(g_agg, r0, r1, tig, Ahi, Alo);
        load_x_frags(hin,   r0, r1, tig, Hhi, Hlo);

        float deg0 = (r0 < N_NODES) ? (float)(g_rowptr[r0 + 1] - g_rowptr[r0]) : 0.f;
        float deg1 = (r1 < N_NODES) ? (float)(g_rowptr[r1 + 1] - g_rowptr[r1]) : 0.f;

        // ---- A-GEMM: C_A = hagg @ W^T + deg*b ----
        float CA[8][4];
#pragma unroll
        for (int nt = 0; nt < 8; nt++)
#pragma unroll
            for (int j = 0; j < 4; j++) CA[nt][j] = 0.f;
        gemm_block(CA, Ahi, Alo, WWh, WWl, 0, lane);
#pragma unroll
        for (int nt = 0; nt < 8; nt++) {
            int c = 8 * nt + 2 * tig;
            CA[nt][0] += deg0 * sbb[c];
            CA[nt][1] += deg0 * sbb[c + 1];
            CA[nt][2] += deg1 * sbb[c];
            CA[nt][3] += deg1 * sbb[c + 1];
        }
        // convert C_A -> A fragments (C(m16n8) slices == A(m16k16) layout)
#pragma unroll
        for (int kt = 0; kt < 4; kt++) {
            split2(make_float2(CA[2 * kt][0],     CA[2 * kt][1]),
                   Ahi[4 * kt + 0], Alo[4 * kt + 0]);
            split2(make_float2(CA[2 * kt][2],     CA[2 * kt][3]),
                   Ahi[4 * kt + 1], Alo[4 * kt + 1]);
            split2(make_float2(CA[2 * kt + 1][0], CA[2 * kt + 1][1]),
                   Ahi[4 * kt + 2], Alo[4 * kt + 2]);
            split2(make_float2(CA[2 * kt + 1][2], CA[2 * kt + 1][3]),
                   Ahi[4 * kt + 3], Alo[4 * kt + 3]);
        }

        // ---- R gate ----
        float P[8][4];
        float CB[8][4];
#pragma unroll
        for (int nt = 0; nt < 8; nt++)
#pragma unroll
            for (int j = 0; j < 4; j++) P[nt][j] = 0.f;
        gemm_block(P, Ahi, Alo, WIHh, WIHl, 0, lane);
        gemm_block(P, Hhi, Hlo, WHHh, WHHl, 0, lane);
#pragma unroll
        for (int nt = 0; nt < 8; nt++) {
            int c = 8 * nt + 2 * tig;
            P[nt][0] = sigmoid_fast(P[nt][0] + sbrz[c]);
            P[nt][1] = sigmoid_fast(P[nt][1] + sbrz[c + 1]);
            P[nt][2] = sigmoid_fast(P[nt][2] + sbrz[c]);
            P[nt][3] = sigmoid_fast(P[nt][3] + sbrz[c + 1]);
        }

        // ---- h_n: P = r * (h@WhhN + bnh) ----
#pragma unroll
        for (int nt = 0; nt < 8; nt++)
#pragma unroll
            for (int j = 0; j < 4; j++) CB[nt][j] = 0.f;
        gemm_block(CB, Hhi, Hlo, WHHh, WHHl, 16, lane);
#pragma unroll
        for (int nt = 0; nt < 8; nt++) {
            int c = 8 * nt + 2 * tig;
            P[nt][0] *= (CB[nt][0] + sbnh[c]);
            P[nt][1] *= (CB[nt][1] + sbnh[c + 1]);
            P[nt][2] *= (CB[nt][2] + sbnh[c]);
            P[nt][3] *= (CB[nt][3] + sbnh[c + 1]);
        }

        // ---- i_n: n = tanh(a@WihN + bni + P) ----
#pragma unroll
        for (int nt = 0; nt < 8; nt++)
#pragma unroll
            for (int j = 0; j < 4; j++) CB[nt][j] = 0.f;
        gemm_block(CB, Ahi, Alo, WIHh, WIHl, 16, lane);
#pragma unroll
        for (int nt = 0; nt < 8; nt++) {
            int c = 8 * nt + 2 * tig;
            P[nt][0] = tanh_fast(CB[nt][0] + sbni[c]     + P[nt][0]);
            P[nt][1] = tanh_fast(CB[nt][1] + sbni[c + 1] + P[nt][1]);
            P[nt][2] = tanh_fast(CB[nt][2] + sbni[c]     + P[nt][2]);
            P[nt][3] = tanh_fast(CB[nt][3] + sbni[c + 1] + P[nt][3]);
        }

        // ---- Z gate + output ----
#pragma unroll
        for (int nt = 0; nt < 8; nt++)
#pragma unroll
            for (int j = 0; j < 4; j++) CB[nt][j] = 0.f;
        gemm_block(CB, Ahi, Alo, WIHh, WIHl, 8, lane);
        gemm_block(CB, Hhi, Hlo, WHHh, WHHl, 8, lane);
#pragma unroll
        for (int nt = 0; nt < 8; nt++) {
            int c = 8 * nt + 2 * tig;
            float z0 = sigmoid_fast(CB[nt][0] + sbrz[64 + c]);
            float z1 = sigmoid_fast(CB[nt][1] + sbrz[64 + c + 1]);
            float z2 = sigmoid_fast(CB[nt][2] + sbrz[64 + c]);
            float z3 = sigmoid_fast(CB[nt][3] + sbrz[64 + c + 1]);
            int fb = 4 * (nt >> 1) + ((nt & 1) ? 2 : 0);
            float2 hrow0 = unsplit2(Hhi[fb],     Hlo[fb]);
            float2 hrow1 = unsplit2(Hhi[fb + 1], Hlo[fb + 1]);
            float o0 = (1.f - z0) * P[nt][0] + z0 * hrow0.x;
            float o1 = (1.f - z1) * P[nt][1] + z1 * hrow0.y;
            float o2 = (1.f - z2) * P[nt][2] + z2 * hrow1.x;
            float o3 = (1.f - z3) * P[nt][3] + z3 * hrow1.y;
            if (r0 < N_NODES)
                *(float2*)&hout[(size_t)r0 * 64 + c] = make_float2(o0, o1);
            if (r1 < N_NODES)
                *(float2*)&hout[(size_t)r1 * 64 + c] = make_float2(o2, o3);
        }
    }
}

// ------------------------- launch ----------------------------------------------
extern "C" void kernel_launch(void* const* d_in, const int* in_sizes, int n_in,
                              void* d_out, int out_size) {
    const float *node_in = 0, *W = 0, *b = 0, *Wih = 0, *Whh = 0, *bih = 0, *bhh = 0;
    const int *src = 0, *dst = 0;
    int n12288 = 0, n192 = 0, n800k = 0;
    for (int i = 0; i < n_in; i++) {
        switch (in_sizes[i]) {
            case N_NODES * D: node_in = (const float*)d_in[i]; break;
            case D * D:       W = (const float*)d_in[i]; break;
            case D:           b = (const float*)d_in[i]; break;
            case 3 * D * D:
                if (n12288++ == 0) Wih = (const float*)d_in[i];
                else               Whh = (const float*)d_in[i];
                break;
            case 3 * D:
                if (n192++ == 0) bih = (const float*)d_in[i];
                else             bhh = (const float*)d_in[i];
                break;
            case N_EDGES:
                if (n800k++ == 0) src = (const int*)d_in[i];
                else              dst = (const int*)d_in[i];
                break;
            default: break;
        }
    }
    float* h = (float*)d_out;

    cudaFuncSetAttribute(gru_kernel, cudaFuncAttributeMaxDynamicSharedMemorySize,
                         SMEM_BYTES);

    const int agg_grid = (N_NODES * 32 + 255) / 256;

    prep_kernel<<<(N_EDGES + 255) / 256, 256>>>(W, Wih, Whh, bih, bhh, dst);
    csr_scan_kernel<<<SCAN_GRID, 512>>>();
    fill_kernel<<<(N_EDGES + 255) / 256, 256>>>(src, dst);

    // step 0
    agg_kernel<<<agg_grid, 256>>>(node_in);
    gru_kernel<<<GRU_GRID, THREADS, SMEM_BYTES>>>(node_in, h, b);
    // step 1
    agg_kernel<<<agg_grid, 256>>>(h);
    gru_kernel<<<GRU_GRID, THREADS, SMEM_BYTES>>>(h, h, b);
    // step 2
    agg_kernel<<<agg_grid, 256>>>(h);
    gru_kernel<<<GRU_GRID, THREADS, SMEM_BYTES>>>(h, h, b);
}